// round 4
// baseline (speedup 1.0000x reference)
#include <cuda_runtime.h>

// Inputs (metadata order):
//   d_in[0] sample       int32  [B,3]      (head, rel, tail)
//   d_in[1] entity_emb   f32    [E,128]
//   d_in[2] relation_emb f32    [R,128]    (unused by the math)
//   d_in[3] type_emb     f32    [T*R, 128*128]
//   d_in[4] node_type    int32  [E]
// Output: f32 [B] scores.
//
// Algebra: score uses only he[0..2]; elementwise normalization means we only
// need rows 0..2 of each 128x128 matrix -> 3 dot products per sample.
//
// Structure: warp-per-sample, single full wave (8192 warps). 512-thread
// blocks -> 512 CTAs (faster launch ramp, better SM quantization than 1024).

#define D    128
#define TLEN 16   // T = type_emb rows / R

__global__ __launch_bounds__(512, 4) void ttd_transe_kernel(
    const int*   __restrict__ sample,
    const float* __restrict__ entity_emb,
    const float* __restrict__ type_emb,
    const int*   __restrict__ node_type,
    float*       __restrict__ out)
{
    const int gwarp = (blockIdx.x * blockDim.x + threadIdx.x) >> 5;
    const int lane  = threadIdx.x & 31;

    // Dependent index chain (lane-uniform -> broadcast, 1 transaction each).
    const int head = __ldg(&sample[gwarp * 3 + 0]);
    const int rel  = __ldg(&sample[gwarp * 3 + 1]);
    const int mrow = rel * TLEN + __ldg(&node_type[head]);

    const float4* __restrict__ h4 =
        reinterpret_cast<const float4*>(entity_emb) + head * (D / 4);
    const float4* __restrict__ m4 =
        reinterpret_cast<const float4*>(type_emb) + mrow * (D * D / 4);

    // Lane l owns floats [4l, 4l+4): four coalesced 512B warp loads.
    // hv depends only on head -> overlaps with the node_type round trip.
    const float4 hv = __ldg(&h4[lane]);
    const float4 r0 = __ldg(&m4[lane]);
    const float4 r1 = __ldg(&m4[32 + lane]);
    const float4 r2 = __ldg(&m4[64 + lane]);

    float s0 = fmaf(hv.x, r0.x, fmaf(hv.y, r0.y, fmaf(hv.z, r0.z, hv.w * r0.w)));
    float s1 = fmaf(hv.x, r1.x, fmaf(hv.y, r1.y, fmaf(hv.z, r1.z, hv.w * r1.w)));
    float s2 = fmaf(hv.x, r2.x, fmaf(hv.y, r2.y, fmaf(hv.z, r2.z, hv.w * r2.w)));

    // Butterfly to 4-lane partials (3 levels x 3 values = 9 shuffles)...
    #pragma unroll
    for (int off = 16; off > 2; off >>= 1) {
        s0 += __shfl_xor_sync(0xFFFFFFFFu, s0, off);
        s1 += __shfl_xor_sync(0xFFFFFFFFu, s1, off);
        s2 += __shfl_xor_sync(0xFFFFFFFFu, s2, off);
    }
    // ...then lane 0 pulls lanes 1..3 directly (6 shuffles, no final butterfly
    // levels for all lanes). Shuffles execute warp-wide; only lane 0's result
    // is used.
    s0 += __shfl_sync(0xFFFFFFFFu, s0, 1) + __shfl_sync(0xFFFFFFFFu, s0, 2)
        + __shfl_sync(0xFFFFFFFFu, s0, 3);
    s1 += __shfl_sync(0xFFFFFFFFu, s1, 1) + __shfl_sync(0xFFFFFFFFu, s1, 2)
        + __shfl_sync(0xFFFFFFFFu, s1, 3);
    s2 += __shfl_sync(0xFFFFFFFFu, s2, 1) + __shfl_sync(0xFFFFFFFFu, s2, 2)
        + __shfl_sync(0xFFFFFFFFu, s2, 3);

    if (lane == 0) {
        const float eps = 1e-12f;
        const float a = s0 / fmaxf(fabsf(s0), eps);
        const float b = s1 / fmaxf(fabsf(s1), eps);
        const float c = s2 / fmaxf(fabsf(s2), eps);
        out[gwarp] = fabsf(a + b - c + 1e-6f);
    }
}

extern "C" void kernel_launch(void* const* d_in, const int* in_sizes, int n_in,
                              void* d_out, int out_size)
{
    const int*   sample     = (const int*)  d_in[0];
    const float* entity_emb = (const float*)d_in[1];
    // d_in[2] relation_emb unused
    const float* type_emb   = (const float*)d_in[3];
    const int*   node_type  = (const int*)  d_in[4];
    float* out = (float*)d_out;

    const int B = out_size;                 // 8192, multiple of 16
    const int threads = 512;                // 16 warps/block, warp per sample
    const int blocks = B / (threads / 32);  // 512

    ttd_transe_kernel<<<blocks, threads>>>(sample, entity_emb, type_emb,
                                           node_type, out);
}

// round 5
// speedup vs baseline: 1.0580x; 1.0580x over previous
#include <cuda_runtime.h>

// Inputs (metadata order):
//   d_in[0] sample       int32  [B,3]      (head, rel, tail)
//   d_in[1] entity_emb   f32    [E,128]
//   d_in[2] relation_emb f32    [R,128]    (unused by the math)
//   d_in[3] type_emb     f32    [T*R, 128*128]
//   d_in[4] node_type    int32  [E]
// Output: f32 [B] scores.
//
// Algebra: score uses only he[0..2]; elementwise normalization means we only
// need rows 0..2 of each 128x128 matrix -> 3 dot products per sample.
//
// Structure: warp-per-sample, single full wave (8192 warps). 128-thread
// blocks -> 2048 CTAs: finest CTA quantization (14-vs-13 blocks/SM, ~7% tail
// skew vs 15% at 1024 CTAs / 33% at 512 CTAs). Total warps identical.

#define D    128
#define TLEN 16   // T = type_emb rows / R

__global__ __launch_bounds__(128) void ttd_transe_kernel(
    const int*   __restrict__ sample,
    const float* __restrict__ entity_emb,
    const float* __restrict__ type_emb,
    const int*   __restrict__ node_type,
    float*       __restrict__ out)
{
    const int gwarp = (blockIdx.x << 2) + (threadIdx.x >> 5);
    const int lane  = threadIdx.x & 31;

    // Level 1: sample indices (lane-uniform broadcast).
    const int head = __ldg(&sample[gwarp * 3 + 0]);
    const int rel  = __ldg(&sample[gwarp * 3 + 1]);

    // Level 2: node_type gather and entity row — both depend only on head,
    // issued together. The rel-dependent matrix base is computed while the
    // node_type load is in flight, so only one IMAD remains after it lands.
    const int nt = __ldg(&node_type[head]);
    const float4* __restrict__ h4 =
        reinterpret_cast<const float4*>(entity_emb) + head * (D / 4);
    const float4 hv = __ldg(&h4[lane]);

    const float4* __restrict__ mbase =
        reinterpret_cast<const float4*>(type_emb) + rel * (TLEN * D * D / 4);
    const float4* __restrict__ m4 = mbase + nt * (D * D / 4);

    // Level 3: matrix rows 0..2 (three coalesced 512B warp loads).
    const float4 r0 = __ldg(&m4[lane]);
    const float4 r1 = __ldg(&m4[32 + lane]);
    const float4 r2 = __ldg(&m4[64 + lane]);

    float s0 = fmaf(hv.x, r0.x, fmaf(hv.y, r0.y, fmaf(hv.z, r0.z, hv.w * r0.w)));
    float s1 = fmaf(hv.x, r1.x, fmaf(hv.y, r1.y, fmaf(hv.z, r1.z, hv.w * r1.w)));
    float s2 = fmaf(hv.x, r2.x, fmaf(hv.y, r2.y, fmaf(hv.z, r2.z, hv.w * r2.w)));

    // Butterfly to 4-lane partials, then lane 0 gathers lanes 1..3 directly.
    #pragma unroll
    for (int off = 16; off > 2; off >>= 1) {
        s0 += __shfl_xor_sync(0xFFFFFFFFu, s0, off);
        s1 += __shfl_xor_sync(0xFFFFFFFFu, s1, off);
        s2 += __shfl_xor_sync(0xFFFFFFFFu, s2, off);
    }
    s0 += __shfl_sync(0xFFFFFFFFu, s0, 1) + __shfl_sync(0xFFFFFFFFu, s0, 2)
        + __shfl_sync(0xFFFFFFFFu, s0, 3);
    s1 += __shfl_sync(0xFFFFFFFFu, s1, 1) + __shfl_sync(0xFFFFFFFFu, s1, 2)
        + __shfl_sync(0xFFFFFFFFu, s1, 3);
    s2 += __shfl_sync(0xFFFFFFFFu, s2, 1) + __shfl_sync(0xFFFFFFFFu, s2, 2)
        + __shfl_sync(0xFFFFFFFFu, s2, 3);

    if (lane == 0) {
        const float eps = 1e-12f;
        const float a = s0 / fmaxf(fabsf(s0), eps);
        const float b = s1 / fmaxf(fabsf(s1), eps);
        const float c = s2 / fmaxf(fabsf(s2), eps);
        out[gwarp] = fabsf(a + b - c + 1e-6f);
    }
}

extern "C" void kernel_launch(void* const* d_in, const int* in_sizes, int n_in,
                              void* d_out, int out_size)
{
    const int*   sample     = (const int*)  d_in[0];
    const float* entity_emb = (const float*)d_in[1];
    // d_in[2] relation_emb unused
    const float* type_emb   = (const float*)d_in[3];
    const int*   node_type  = (const int*)  d_in[4];
    float* out = (float*)d_out;

    const int B = out_size;                 // 8192, multiple of 4
    const int threads = 128;                // 4 warps/block, warp per sample
    const int blocks = B / 4;               // 2048

    ttd_transe_kernel<<<blocks, threads>>>(sample, entity_emb, type_emb,
                                           node_type, out);
}